// round 1
// baseline (speedup 1.0000x reference)
#include <cuda_runtime.h>

// Problem constants (shapes fixed by the dataset)
#define NMAX 100000
#define EMAX 800000

// Scratch (no allocation allowed -> __device__ globals)
__device__ float g_xl[NMAX * 128];
__device__ float g_xr[NMAX * 128];
__device__ float g_h [NMAX * 64];
__device__ int   g_cnt[NMAX];
__device__ int   g_rowptr[NMAX + 1];
__device__ int   g_fill[NMAX];
__device__ int   g_adj[EMAX];
__device__ int   g_bsum[128];

// ---------------------------------------------------------------------------
// CSR build: histogram over dst, exclusive scan, scatter src
// ---------------------------------------------------------------------------
__global__ void k_zero(int N) {
    int i = blockIdx.x * blockDim.x + threadIdx.x;
    if (i < N) g_cnt[i] = 0;
}

__global__ void k_hist(const int* __restrict__ ei, int E) {
    for (int i = blockIdx.x * blockDim.x + threadIdx.x; i < E; i += gridDim.x * blockDim.x)
        atomicAdd(&g_cnt[ei[E + i]], 1);
}

__device__ __forceinline__ int block_scan_excl_1024(int val, int& total) {
    __shared__ int wsum[32];
    int lane = threadIdx.x & 31;
    int w    = threadIdx.x >> 5;
    int inc  = val;
#pragma unroll
    for (int o = 1; o < 32; o <<= 1) {
        int u = __shfl_up_sync(0xffffffffu, inc, o);
        if (lane >= o) inc += u;
    }
    if (lane == 31) wsum[w] = inc;
    __syncthreads();
    if (w == 0) {
        int v = wsum[lane];
#pragma unroll
        for (int o = 1; o < 32; o <<= 1) {
            int u = __shfl_up_sync(0xffffffffu, v, o);
            if (lane >= o) v += u;
        }
        wsum[lane] = v;
    }
    __syncthreads();
    int off = (w > 0) ? wsum[w - 1] : 0;
    total = wsum[31];
    return off + inc - val;  // exclusive
}

__global__ void k_scan1(int N) {
    int idx = blockIdx.x * 1024 + threadIdx.x;
    int val = (idx < N) ? g_cnt[idx] : 0;
    int total;
    int ex = block_scan_excl_1024(val, total);
    if (idx < N) g_rowptr[idx] = ex;
    if (threadIdx.x == 0) g_bsum[blockIdx.x] = total;
}

__global__ void k_scan2(int NB) {
    __shared__ int s[1024];
    int t = threadIdx.x;
    s[t] = (t < NB) ? g_bsum[t] : 0;
    __syncthreads();
    for (int o = 1; o < 1024; o <<= 1) {
        int v = (t >= o) ? s[t - o] : 0;
        __syncthreads();
        s[t] += v;
        __syncthreads();
    }
    if (t < NB) g_bsum[t] = (t > 0) ? s[t - 1] : 0;  // exclusive
}

__global__ void k_scan3(int N, int E) {
    int idx = blockIdx.x * 1024 + threadIdx.x;
    if (idx < N) {
        int r = g_rowptr[idx] + g_bsum[blockIdx.x];
        g_rowptr[idx] = r;
        g_fill[idx]   = r;
    }
    if (idx == 0) g_rowptr[N] = E;
}

__global__ void k_scatter(const int* __restrict__ ei, int E) {
    for (int i = blockIdx.x * blockDim.x + threadIdx.x; i < E; i += gridDim.x * blockDim.x) {
        int d = ei[E + i];
        int p = atomicAdd(&g_fill[d], 1);
        g_adj[p] = ei[i];
    }
}

// ---------------------------------------------------------------------------
// GEMM: Y = X(64-wide rows) @ W. DUAL computes two W's in one pass (TOT=128).
// W resident in SMEM (32 KB); warp owns RPT=8 rows -> each SMEM W read is
// amortized over 8 rows (32 FFMA per LDS.128).
// ---------------------------------------------------------------------------
template <int OUTC, bool DUAL>
__global__ void k_gemm(const float* __restrict__ X, const float* __restrict__ W0,
                       const float* __restrict__ W1, float* __restrict__ Y0,
                       float* __restrict__ Y1, int N) {
    constexpr int TOT = DUAL ? 2 * OUTC : OUTC;  // 128 in all uses
    constexpr int CPT = TOT / 32;                // 4
    constexpr int RPT = 8;
    __shared__ float Ws[64 * TOT];

    if (DUAL) {
        for (int i = threadIdx.x; i < 64 * OUTC; i += blockDim.x) {
            int k = i / OUTC, j = i - k * OUTC;
            Ws[k * TOT + j]        = W0[i];
            Ws[k * TOT + OUTC + j] = W1[i];
        }
    } else {
        for (int i = threadIdx.x; i < 64 * TOT; i += blockDim.x) Ws[i] = W0[i];
    }
    __syncthreads();

    const int lane = threadIdx.x & 31;
    const int wid  = threadIdx.x >> 5;
    const int nw   = blockDim.x >> 5;

    for (int base = (blockIdx.x * nw + wid) * RPT; base < N; base += gridDim.x * nw * RPT) {
        float xa[RPT], xb[RPT];
#pragma unroll
        for (int r = 0; r < RPT; r++) {
            int row  = base + r;
            bool ok  = row < N;
            xa[r] = ok ? X[row * 64 + lane]      : 0.f;
            xb[r] = ok ? X[row * 64 + 32 + lane] : 0.f;
        }
        float acc[RPT][CPT];
#pragma unroll
        for (int r = 0; r < RPT; r++)
#pragma unroll
            for (int j = 0; j < CPT; j++) acc[r][j] = 0.f;

#pragma unroll
        for (int k = 0; k < 64; k++) {
            float4 w = *(const float4*)&Ws[k * TOT + lane * CPT];
#pragma unroll
            for (int r = 0; r < RPT; r++) {
                float xk = __shfl_sync(0xffffffffu, (k < 32) ? xa[r] : xb[r], k & 31);
                acc[r][0] += xk * w.x;
                acc[r][1] += xk * w.y;
                acc[r][2] += xk * w.z;
                acc[r][3] += xk * w.w;
            }
        }
#pragma unroll
        for (int r = 0; r < RPT; r++) {
            int row = base + r;
            if (row >= N) break;
            int c = lane * CPT;
            float4 o = make_float4(acc[r][0], acc[r][1], acc[r][2], acc[r][3]);
            if (DUAL) {
                if (c < OUTC) *(float4*)&Y0[row * OUTC + c] = o;
                else          *(float4*)&Y1[row * OUTC + (c - OUTC)] = o;
            } else {
                *(float4*)&Y0[row * TOT + c] = o;
            }
        }
    }
}

// ---------------------------------------------------------------------------
// Fused GATv2 edge phase: one warp per destination node, online softmax.
// Layers 1/2: H=4, C=16 (64 feats, float2 per lane), output = ELU(out + bias)
// ---------------------------------------------------------------------------
__device__ __forceinline__ float leaky(float t) { return t > 0.f ? t : 0.2f * t; }

__global__ void k_edge64(const float* __restrict__ XL, const float* __restrict__ XR,
                         const float* __restrict__ att, const float* __restrict__ bias,
                         float* __restrict__ OUT, int N) {
    int lane = threadIdx.x & 31;
    int n    = (blockIdx.x * blockDim.x + threadIdx.x) >> 5;
    if (n >= N) return;

    float a0 = att[2 * lane], a1 = att[2 * lane + 1];
    float2 xr = *(const float2*)&XR[n * 64 + 2 * lane];
    float2 vs = *(const float2*)&XL[n * 64 + 2 * lane];

    // self edge
    float p = a0 * leaky(vs.x + xr.x) + a1 * leaky(vs.y + xr.y);
    p += __shfl_xor_sync(0xffffffffu, p, 4);
    p += __shfl_xor_sync(0xffffffffu, p, 2);
    p += __shfl_xor_sync(0xffffffffu, p, 1);
    float m = p, d = 1.f, ax = vs.x, ay = vs.y;

    int beg = g_rowptr[n], end = g_rowptr[n + 1];
    for (int i = beg; i < end; i++) {
        int s = g_adj[i];
        float2 v = *(const float2*)&XL[s * 64 + 2 * lane];
        p = a0 * leaky(v.x + xr.x) + a1 * leaky(v.y + xr.y);
        p += __shfl_xor_sync(0xffffffffu, p, 4);
        p += __shfl_xor_sync(0xffffffffu, p, 2);
        p += __shfl_xor_sync(0xffffffffu, p, 1);
        if (p <= m) {
            float w = __expf(p - m);
            ax += w * v.x; ay += w * v.y; d += w;
        } else {
            float sc = __expf(m - p);
            ax = ax * sc + v.x; ay = ay * sc + v.y; d = d * sc + 1.f;
            m = p;
        }
    }
    float inv = 1.f / d;
    float ox = ax * inv + bias[2 * lane];
    float oy = ay * inv + bias[2 * lane + 1];
    ox = ox > 0.f ? ox : (__expf(ox) - 1.f);  // ELU
    oy = oy > 0.f ? oy : (__expf(oy) - 1.f);
    *(float2*)&OUT[n * 64 + 2 * lane] = make_float2(ox, oy);
}

// Layer 3: H=4, C=32 (128 feats, float4 per lane), mean over heads + bias
__global__ void k_edge128_mean(const float* __restrict__ XL, const float* __restrict__ XR,
                               const float* __restrict__ att, const float* __restrict__ bias,
                               float* __restrict__ OUT, int N) {
    int lane = threadIdx.x & 31;
    int n    = (blockIdx.x * blockDim.x + threadIdx.x) >> 5;
    if (n >= N) return;

    float4 a  = *(const float4*)&att[4 * lane];
    float4 xr = *(const float4*)&XR[n * 128 + 4 * lane];
    float4 vs = *(const float4*)&XL[n * 128 + 4 * lane];

    float p = a.x * leaky(vs.x + xr.x) + a.y * leaky(vs.y + xr.y) +
              a.z * leaky(vs.z + xr.z) + a.w * leaky(vs.w + xr.w);
    p += __shfl_xor_sync(0xffffffffu, p, 4);
    p += __shfl_xor_sync(0xffffffffu, p, 2);
    p += __shfl_xor_sync(0xffffffffu, p, 1);
    float m = p, d = 1.f;
    float4 acc = vs;

    int beg = g_rowptr[n], end = g_rowptr[n + 1];
    for (int i = beg; i < end; i++) {
        int s = g_adj[i];
        float4 v = *(const float4*)&XL[s * 128 + 4 * lane];
        p = a.x * leaky(v.x + xr.x) + a.y * leaky(v.y + xr.y) +
            a.z * leaky(v.z + xr.z) + a.w * leaky(v.w + xr.w);
        p += __shfl_xor_sync(0xffffffffu, p, 4);
        p += __shfl_xor_sync(0xffffffffu, p, 2);
        p += __shfl_xor_sync(0xffffffffu, p, 1);
        if (p <= m) {
            float w = __expf(p - m);
            acc.x += w * v.x; acc.y += w * v.y; acc.z += w * v.z; acc.w += w * v.w;
            d += w;
        } else {
            float sc = __expf(m - p);
            acc.x = acc.x * sc + v.x; acc.y = acc.y * sc + v.y;
            acc.z = acc.z * sc + v.z; acc.w = acc.w * sc + v.w;
            d = d * sc + 1.f;
            m = p;
        }
    }
    float inv = 1.f / d;
    float o0 = acc.x * inv, o1 = acc.y * inv, o2 = acc.z * inv, o3 = acc.w * inv;
    // mean over 4 heads: sum lanes {l, l^8, l^16, l^24}
#pragma unroll
    for (int off = 8; off <= 16; off <<= 1) {
        o0 += __shfl_xor_sync(0xffffffffu, o0, off);
        o1 += __shfl_xor_sync(0xffffffffu, o1, off);
        o2 += __shfl_xor_sync(0xffffffffu, o2, off);
        o3 += __shfl_xor_sync(0xffffffffu, o3, off);
    }
    if (lane < 8) {
        int c = 4 * lane;
        float4 o = make_float4(0.25f * o0 + bias[c + 0],
                               0.25f * o1 + bias[c + 1],
                               0.25f * o2 + bias[c + 2],
                               0.25f * o3 + bias[c + 3]);
        *(float4*)&OUT[n * 32 + c] = o;
    }
}

// ---------------------------------------------------------------------------
// Launch
// ---------------------------------------------------------------------------
extern "C" void kernel_launch(void* const* d_in, const int* in_sizes, int n_in,
                              void* d_out, int out_size) {
    const float* x   = (const float*)d_in[0];
    const int*   ei  = (const int*)  d_in[1];
    const float* W1l = (const float*)d_in[2];
    const float* W1r = (const float*)d_in[3];
    const float* a1  = (const float*)d_in[4];
    const float* b1  = (const float*)d_in[5];
    const float* W2l = (const float*)d_in[6];
    const float* W2r = (const float*)d_in[7];
    const float* a2  = (const float*)d_in[8];
    const float* b2  = (const float*)d_in[9];
    const float* W3l = (const float*)d_in[10];
    const float* W3r = (const float*)d_in[11];
    const float* a3  = (const float*)d_in[12];
    const float* b3  = (const float*)d_in[13];
    float* out = (float*)d_out;

    const int N = in_sizes[0] / 64;
    const int E = in_sizes[1] / 2;
    const int NB = (N + 1023) / 1024;

    float *xl, *xr, *h;
    cudaGetSymbolAddress((void**)&xl, g_xl);
    cudaGetSymbolAddress((void**)&xr, g_xr);
    cudaGetSymbolAddress((void**)&h,  g_h);

    // CSR build (per replay: deterministic work)
    k_zero<<<(N + 255) / 256, 256>>>(N);
    k_hist<<<1024, 256>>>(ei, E);
    k_scan1<<<NB, 1024>>>(N);
    k_scan2<<<1, 1024>>>(NB);
    k_scan3<<<NB, 1024>>>(N, E);
    k_scatter<<<1024, 256>>>(ei, E);

    const int GB = (N + 63) / 64;        // gemm: 8 warps * 8 rows per block
    const int EB = (N + 7) / 8;          // edge: 8 warps (nodes) per block

    // Layer 1
    k_gemm<64, true><<<GB, 256>>>(x, W1l, W1r, xl, xr, N);
    k_edge64<<<EB, 256>>>(xl, xr, a1, b1, h, N);
    // Layer 2
    k_gemm<64, true><<<GB, 256>>>(h, W2l, W2r, xl, xr, N);
    k_edge64<<<EB, 256>>>(xl, xr, a2, b2, h, N);
    // Layer 3
    k_gemm<128, false><<<GB, 256>>>(h, W3l, nullptr, xl, nullptr, N);
    k_gemm<128, false><<<GB, 256>>>(h, W3r, nullptr, xr, nullptr, N);
    k_edge128_mean<<<EB, 256>>>(xl, xr, a3, b3, out, N);
}